// round 6
// baseline (speedup 1.0000x reference)
#include <cuda_runtime.h>
#include <cuda_fp16.h>
#include <cstdint>

#define TB_ 131072
#define B_  32

// ---------------- device scratch (no allocation allowed) ----------------
__device__ float  g_hbre[B_ * 512];            // [b][nt*128 + hl*4 + q]
__device__ uint2  g_wfrag[4 * 16 * 8 * 32];    // [nt][nf][ks][lane] -> {b0,b1}
__device__ __half g_ah[(size_t)TB_ * 128];     // fp16 A, pre-swizzled (33.5 MB)

// ---------------- helpers ----------------
__device__ __forceinline__ uint32_t smem_u32(const void* p) {
    uint32_t a;
    asm("{ .reg .u64 t; cvta.to.shared.u64 t, %1; cvt.u32.u64 %0, t; }" : "=r"(a) : "l"(p));
    return a;
}
__device__ __forceinline__ float tanh_ap(float x) {
    float y; asm("tanh.approx.f32 %0, %1;" : "=f"(y) : "f"(x)); return y;
}
__device__ __forceinline__ float sig_ap(float x) { return fmaf(tanh_ap(x * 0.5f), 0.5f, 0.5f); }

// ---------------- fused prep kernel ----------------
// blocks [0,64):   Hb = h0 @ W_hh^T + b_ih + b_hh  (reordered)
// blocks [64,128): W_ih -> fp16 B-fragment-major
// blocks [128,8320): input fp32 -> fp16, swizzled, into g_ah
__global__ void prep_all(const float* __restrict__ input, const float* __restrict__ h0,
                         const float* __restrict__ W_hh, const float* __restrict__ b_ih,
                         const float* __restrict__ b_hh, const float* __restrict__ W_ih) {
    const int bx = blockIdx.x, tid = threadIdx.x;
    if (bx < 64) {
        int idx = bx * 256 + tid;                 // 0..16383
        int b = idx & 31, g = idx >> 5;
        const float4* wv = (const float4*)(W_hh + g * 128);
        const float4* hv = (const float4*)(h0 + b * 128);
        float s0 = b_ih[g] + b_hh[g], s1 = 0.f, s2 = 0.f, s3 = 0.f;
#pragma unroll
        for (int k = 0; k < 32; k++) {
            float4 w = wv[k], h = hv[k];
            s0 += w.x * h.x; s1 += w.y * h.y; s2 += w.z * h.z; s3 += w.w * h.w;
        }
        float s = (s0 + s1) + (s2 + s3);
        int q = g >> 7, rest = g & 127, nt = rest >> 5, hl = rest & 31;
        g_hbre[b * 512 + nt * 128 + hl * 4 + q] = s;
    } else if (bx < 128) {
        // mma.m16n8k16 B frag: b0={B[k0][n],B[k0+1][n]}, b1={B[k0+8][n],B[k0+9][n]}
        // k0 = ks*16 + (lane&3)*2, n = nf*8 + (lane>>2); gate-interleaved n = hl*4 + q
        int idx = (bx - 64) * 256 + tid;          // 0..16383
        int l = idx & 31, ks = (idx >> 5) & 7, nf = (idx >> 8) & 15, nt = idx >> 12;
        int t = l & 3, gq = l >> 2;
        int n = nf * 8 + gq;
        int k0 = ks * 16 + t * 2;
        int g = (n & 3) * 128 + nt * 32 + (n >> 2);
        const float* wr = W_ih + g * 128;
        __half2 b0 = __floats2half2_rn(wr[k0], wr[k0 + 1]);
        __half2 b1 = __floats2half2_rn(wr[k0 + 8], wr[k0 + 9]);
        g_wfrag[idx] = make_uint2(*(uint32_t*)&b0, *(uint32_t*)&b1);
    } else {
        // A convert: chunk ci handles 8 halfs (16B) of one row, swizzled for ldmatrix
        int ci = (bx - 128) * 256 + tid;          // 0 .. TB_*16-1
        int row = ci >> 4, c = ci & 15;
        const float4* ip = (const float4*)input;
        float4 v0 = ip[(size_t)row * 32 + c * 2];
        float4 v1 = ip[(size_t)row * 32 + c * 2 + 1];
        __half2 h0p = __floats2half2_rn(v0.x, v0.y);
        __half2 h1p = __floats2half2_rn(v0.z, v0.w);
        __half2 h2p = __floats2half2_rn(v1.x, v1.y);
        __half2 h3p = __floats2half2_rn(v1.z, v1.w);
        uint32_t off = (uint32_t)row * 256 + (((uint32_t)c * 16) ^ (((uint32_t)row & 7) << 4));
        uint4 pk = make_uint4(*(uint32_t*)&h0p, *(uint32_t*)&h1p, *(uint32_t*)&h2p, *(uint32_t*)&h3p);
        *(uint4*)((char*)g_ah + off) = pk;
    }
}

// ---------------- main kernel ----------------
#define SMEM_A   0                 // 32768 B : A fp16 swizzled (aliases Hs f32 in epilogue)
#define SMEM_B   32768             // 32768 B : B frags (uint2 x 4096)
#define SMEM_HB  65536             // 16896 B : HBs [32][132] f32
#define SMEM_C0  (65536 + 16896)   // 4224  B : c0   [32][33]
#define SMEM_NZ  (SMEM_C0 + 4224)  // 4224  B : noise[32][33]
#define SMEM_TOT (SMEM_NZ + 4224)  // 90880 B

__global__ __launch_bounds__(256, 2)
void lstm_mma(const float* __restrict__ c0, const float* __restrict__ noise,
              float* __restrict__ out) {
    extern __shared__ char sm[];
    uint2* Bs  = (uint2*)(sm + SMEM_B);
    float* HBs = (float*)(sm + SMEM_HB);
    float* C0s = (float*)(sm + SMEM_C0);
    float* NZs = (float*)(sm + SMEM_NZ);
    float* Hs  = (float*)sm;               // aliases A region during epilogue

    const int tid = threadIdx.x;
    const int wid = tid >> 5, lane = tid & 31;
    const int nt = blockIdx.x & 3, grp = blockIdx.x >> 2;
    const int wm = wid & 1, wn = wid >> 1;            // 2 x 4 warp grid (64m x 32n)
    const uint32_t smb = smem_u32(sm);

    // ---- stage B fragments, HB, c0, noise (once per CTA) ----
    {
        const uint2* src = g_wfrag + nt * 4096;
        for (int i = tid; i < 4096; i += 256) Bs[i] = src[i];
        for (int i = tid; i < 4096; i += 256) {
            int b = i >> 7, c = i & 127;
            HBs[b * 132 + c] = g_hbre[b * 512 + nt * 128 + c];
        }
        for (int i = tid; i < 1024; i += 256) {
            int b = i >> 5, hl = i & 31;
            C0s[b * 33 + hl] = c0[b * 128 + nt * 32 + hl];
            NZs[b * 33 + hl] = noise[b * 128 + nt * 32 + hl];
        }
    }

    // per-lane ldmatrix address pieces
    const int arow = lane & 15;
    const uint32_t a_sw = (uint32_t)(arow & 7) << 4;
    const uint32_t a_colb = (uint32_t)(lane >> 4) * 16;
    const int t = lane & 3, g = lane >> 2, odd = lane & 1;

    for (int it = 0; it < 4; it++) {
        const int mt = grp * 4 + it;
        const long r0 = (long)mt * 128;
        __syncthreads();                               // A/Hs buffer free

        // ---- A tile: raw 32KB byte-copy (pre-converted, pre-swizzled) ----
        {
            const char* gsrc = (const char*)g_ah + r0 * 256;
            uint32_t sdst = smb + SMEM_A + (uint32_t)tid * 16;
            const char* gp = gsrc + (uint32_t)tid * 16;
#pragma unroll
            for (int j = 0; j < 8; j++) {
                asm volatile("cp.async.cg.shared.global [%0], [%1], 16;"
                             :: "r"(sdst + j * 4096), "l"(gp + j * 4096));
            }
            asm volatile("cp.async.commit_group;");
            asm volatile("cp.async.wait_group 0;" ::: "memory");
        }
        __syncthreads();

        // ---- tensor-core GEMM ----
        float acc[4][4][4];
#pragma unroll
        for (int mf = 0; mf < 4; mf++)
#pragma unroll
            for (int nf = 0; nf < 4; nf++)
#pragma unroll
                for (int r = 0; r < 4; r++) acc[mf][nf][r] = 0.f;

#pragma unroll
        for (int ks = 0; ks < 8; ks++) {
            uint2 bfr[4];
#pragma unroll
            for (int nf = 0; nf < 4; nf++)
                bfr[nf] = Bs[((wn * 4 + nf) * 8 + ks) * 32 + lane];
#pragma unroll
            for (int mf = 0; mf < 4; mf++) {
                uint32_t row = (uint32_t)(wm * 64 + mf * 16 + arow);
                uint32_t addr = smb + SMEM_A + row * 256 + (((uint32_t)(ks * 32) + a_colb) ^ a_sw);
                uint32_t a0, a1, a2, a3;
                asm volatile("ldmatrix.sync.aligned.m8n8.x4.shared.b16 {%0,%1,%2,%3}, [%4];"
                             : "=r"(a0), "=r"(a1), "=r"(a2), "=r"(a3) : "r"(addr));
#pragma unroll
                for (int nf = 0; nf < 4; nf++) {
                    asm volatile(
                        "mma.sync.aligned.m16n8k16.row.col.f32.f16.f16.f32 "
                        "{%0,%1,%2,%3}, {%4,%5,%6,%7}, {%8,%9}, {%0,%1,%2,%3};"
                        : "+f"(acc[mf][nf][0]), "+f"(acc[mf][nf][1]),
                          "+f"(acc[mf][nf][2]), "+f"(acc[mf][nf][3])
                        : "r"(a0), "r"(a1), "r"(a2), "r"(a3),
                          "r"(bfr[nf].x), "r"(bfr[nf].y));
                }
            }
        }
        __syncthreads();                               // A reads done; Hs may overwrite

        // ---- fused LSTM epilogue ----
#pragma unroll
        for (int mf = 0; mf < 4; mf++) {
#pragma unroll
            for (int nf = 0; nf < 4; nf++) {
                float c0r = acc[mf][nf][0], c1r = acc[mf][nf][1];
                float c2r = acc[mf][nf][2], c3r = acc[mf][nf][3];
                float v0 = __shfl_xor_sync(0xffffffffu, c0r, 1);
                float v1 = __shfl_xor_sync(0xffffffffu, c1r, 1);
                float v2 = __shfl_xor_sync(0xffffffffu, c2r, 1);
                float v3 = __shfl_xor_sync(0xffffffffu, c3r, 1);
                float g0, g1, g2, g3;
                if (!odd) { g0 = c0r; g1 = c1r; g2 = v0; g3 = v1; }
                else      { g0 = v2;  g1 = v3;  g2 = c2r; g3 = c3r; }
                int row = wm * 64 + mf * 16 + g + (odd ? 8 : 0);
                int hl  = wn * 8 + nf * 2 + (t >> 1);
                int b   = row & 31;
                float4 hb = *(float4*)(HBs + b * 132 + hl * 4);
                float gi = g0 + hb.x, gf = g1 + hb.y, gg = g2 + hb.z, go = g3 + hb.w;
                float si = sig_ap(gi), sf = sig_ap(gf), so = sig_ap(go);
                float tg = tanh_ap(gg);
                float cc = sf * C0s[b * 33 + hl] + si * tg;
                float hv = so * tanh_ap(cc) + NZs[b * 33 + hl];
                Hs[row * 36 + hl] = hv;
                long gr = r0 + row;
                if (gr >= (long)TB_ - 32) {            // last timestep rows
                    long base = (long)TB_ * 128 + (long)b * 128 + nt * 32 + hl;
                    out[base] = hv;                    // h_last
                    out[base + 32 * 128] = cc;         // c_last
                }
            }
        }
        __syncthreads();

        // ---- coalesced store of h tile ----
#pragma unroll
        for (int j = 0; j < 4; j++) {
            int i4 = tid + j * 256;
            int row = i4 >> 3, hq = i4 & 7;
            float4 hv = *(float4*)(Hs + row * 36 + hq * 4);
            *(float4*)(out + (r0 + row) * 128 + nt * 32 + hq * 4) = hv;
        }
    }
}

// ---------------- launch ----------------
extern "C" void kernel_launch(void* const* d_in, const int* in_sizes, int n_in,
                              void* d_out, int out_size) {
    const float* input = (const float*)d_in[0];
    const float* h0    = (const float*)d_in[1];
    const float* c0    = (const float*)d_in[2];
    const float* noise = (const float*)d_in[3];
    const float* W_ih  = (const float*)d_in[4];
    const float* W_hh  = (const float*)d_in[5];
    const float* b_ih  = (const float*)d_in[6];
    const float* b_hh  = (const float*)d_in[7];
    float* out = (float*)d_out;

    prep_all<<<128 + TB_ * 16 / 256, 256>>>(input, h0, W_hh, b_ih, b_hh, W_ih);

    cudaFuncSetAttribute(lstm_mma, cudaFuncAttributeMaxDynamicSharedMemorySize, SMEM_TOT);
    lstm_mma<<<1024, 256, SMEM_TOT>>>(c0, noise, out);
}